// round 16
// baseline (speedup 1.0000x reference)
#include <cuda_runtime.h>
#include <mma.h>
#include <cstdint>
using namespace nvcuda;

#define B_ 8
#define N_ 1024
#define H_ 768
#define NH_ 12
#define M_ 256
#define ST 72
#define STP 40
#define KT 32
#define NKT 24
#define LOG2E 1.4426950408889634f

// ---------------- scratch ----------------
__device__ float g_xr[B_*N_*H_];
__device__ float g_vi[B_*N_*H_];
__device__ float g_Wr[4*H_*H_];
__device__ float g_Qb[B_*N_*H_];
__device__ float g_Kb[B_*N_*H_];
__device__ float g_sc[B_*N_];
__device__ float g_vg2[B_*N_];
__device__ float g_ab[B_*N_];
__device__ float g_dg[B_*N_];
__device__ float g_c1[B_*N_];
__device__ float g_c2[B_*N_];
__device__ float g_cs1[B_];
__device__ float g_cs2[B_];
__device__ float g_Z[B_*NH_*N_];
__device__ float g_r1[B_*NH_*N_];
__device__ float g_r2[B_*NH_*N_];
__device__ float g_y1[B_*NH_*H_];
__device__ float g_y2[B_*NH_*H_];
__device__ float g_A1[B_*H_];
__device__ float g_A2[B_*H_];
__device__ float g_u1[B_*H_];
__device__ float g_u2[B_*H_];

__device__ __forceinline__ bool d_pred(const int* P, int i){ return P[i]==1; }
__device__ __forceinline__ bool d_single(const int* P, int i){ return (i==0) || (i>=2 && P[i-2]==1); }
__device__ __forceinline__ float d_lrelu(float t){ return t >= 0.f ? t : 0.02f*t; }
__device__ __forceinline__ float tf32r(float x){ return wmma::__float_to_tf32(x); }
__device__ __forceinline__ float fex2(float x){ float y; asm("ex2.approx.f32 %0, %1;" : "=f"(y) : "f"(x)); return y; }
__device__ __forceinline__ float ftanh(float x){ float y; asm("tanh.approx.f32 %0, %1;" : "=f"(y) : "f"(x)); return y; }

__device__ __forceinline__ void perm_store(float* dst, float4 a, float4 b){
  float4 o0 = make_float4(tf32r(a.x), tf32r(b.x), tf32r(a.y), tf32r(b.y));
  float4 o1 = make_float4(tf32r(a.z), tf32r(b.z), tf32r(a.w), tf32r(b.w));
  *(float4*)dst = o0; *(float4*)(dst+4) = o1;
}

// ---------------- cp.async ----------------
__device__ __forceinline__ void cpa16s(uint32_t s, const float* g){
  asm volatile("cp.async.cg.shared.global [%0], [%1], 16;\n" :: "r"(s), "l"(g));
}
__device__ __forceinline__ void cp_commit(){ asm volatile("cp.async.commit_group;\n"); }
__device__ __forceinline__ void cp_wait0(){ asm volatile("cp.async.wait_group 0;\n"); }

// ---------------- m16n8k8 tf32 mma.sync ----------------
__device__ __forceinline__ void mma8(float c[4], const uint32_t a[4], uint32_t b0, uint32_t b1){
  asm volatile(
    "mma.sync.aligned.m16n8k8.row.col.f32.tf32.tf32.f32 "
    "{%0,%1,%2,%3}, {%4,%5,%6,%7}, {%8,%9}, {%0,%1,%2,%3};\n"
    : "+f"(c[0]), "+f"(c[1]), "+f"(c[2]), "+f"(c[3])
    : "r"(a[0]), "r"(a[1]), "r"(a[2]), "r"(a[3]), "r"(b0), "r"(b1));
}

template<int STRIDE, int NF, int K8>
__device__ __forceinline__ void mma_tile_pre(const float* __restrict__ mA,
                                             const float* __restrict__ mB,
                                             float c[2][NF][4]){
  #pragma unroll
  for (int k8=0;k8<K8;k8++){
    uint32_t a[2][4];
    #pragma unroll
    for (int rf=0; rf<2; rf++){
      float2 v0 = *(const float2*)(mA + rf*16*STRIDE + k8*8);
      float2 v1 = *(const float2*)(mA + rf*16*STRIDE + 8*STRIDE + k8*8);
      a[rf][0]=__float_as_uint(v0.x); a[rf][2]=__float_as_uint(v0.y);
      a[rf][1]=__float_as_uint(v1.x); a[rf][3]=__float_as_uint(v1.y);
    }
    #pragma unroll
    for (int nf=0;nf<NF;nf++){
      float2 bv = *(const float2*)(mB + nf*8*STRIDE + k8*8);
      mma8(c[0][nf], a[0], __float_as_uint(bv.x), __float_as_uint(bv.y));
      mma8(c[1][nf], a[1], __float_as_uint(bv.x), __float_as_uint(bv.y));
    }
  }
}

// ---------------- init ----------------
__global__ void k_init(const float* __restrict__ bsc){
  int i = blockIdx.x*blockDim.x + threadIdx.x;
  if (i < B_*N_){ g_vg2[i] = 0.f; g_sc[i] = bsc[0]; }
  if (i < B_*NH_*H_){ g_y1[i]=0.f; g_y2[i]=0.f; }
  if (i < B_*NH_*N_){ g_Z[i]=0.f; g_r1[i]=0.f; g_r2[i]=0.f; }
}

// ---------------- preconv (x, var_in, 4 weights) ----------------
__global__ void k_preconv(const float* __restrict__ x, const int* __restrict__ pp,
                          const float* __restrict__ W0, const float* __restrict__ W1,
                          const float* __restrict__ W2, const float* __restrict__ W3){
  const int XT8 = B_*N_*H_/8;
  const int WT8 = H_*H_/8;
  const int H8 = H_/8;
  int i = blockIdx.x*blockDim.x + threadIdx.x;
  if (i < XT8){
    const float4* s = (const float4*)x + (size_t)i*2;
    perm_store(g_xr + (size_t)i*8, s[0], s[1]);
  } else if (i < 2*XT8){
    int j = i - XT8;
    int hh8 = j % H8;
    int nn  = (j / H8) % N_;
    int b   = j / (N_*H8);
    bool single = (nn==0) || (nn>=2 && pp[b*N_+nn-2]==1);
    int np = (nn+1)&(N_-1), nm = (nn+N_-1)&(N_-1);
    const float* bp = x + ((size_t)b*N_ + np)*H_ + hh8*8;
    float4 xa = *(const float4*)bp, xb = *(const float4*)(bp+4);
    if (!single){
      const float* bm = x + ((size_t)b*N_ + nm)*H_ + hh8*8;
      float4 ya = *(const float4*)bm, yb = *(const float4*)(bm+4);
      xa.x=0.5f*(xa.x+ya.x); xa.y=0.5f*(xa.y+ya.y); xa.z=0.5f*(xa.z+ya.z); xa.w=0.5f*(xa.w+ya.w);
      xb.x=0.5f*(xb.x+yb.x); xb.y=0.5f*(xb.y+yb.y); xb.z=0.5f*(xb.z+yb.z); xb.w=0.5f*(xb.w+yb.w);
    }
    perm_store(g_vi + (size_t)j*8, xa, xb);
  } else {
    int j = i - 2*XT8;
    if (j < 4*WT8){
      int w = j / WT8, o = j - w*WT8;
      int row = o / H8, rem = o - row*H8;
      int srow = row;
      if (w==2 || w==3){
        int r8 = row & 7;
        srow = (row & ~7) | ((r8&1)*4 + (r8>>1));
      }
      const float* src = (w==0)?W0:(w==1)?W1:(w==2)?W2:W3;
      const float4* s = (const float4*)(src + (size_t)srow*H_ + rem*8);
      perm_store(g_Wr + (size_t)w*H_*H_ + (size_t)o*8, s[0], s[1]);
    }
  }
}

// ---------------- merged projections: sel=1 -> modes {0,1}; sel=0 -> modes {2,3} ----------------
__global__ __launch_bounds__(256,2) void k_proj(
    const float* __restrict__ b_var, const float* __restrict__ b_sym,
    const float* __restrict__ b_q, const float* __restrict__ b_k,
    const float* __restrict__ Wsc,
    float* __restrict__ Qb, float* __restrict__ Kb, int sel){
  extern __shared__ float sm[];
  int z = blockIdx.z;
  int mode = sel ? z : (z+2);
  const float* A = (mode==0) ? g_vi : g_xr;
  const float* W = g_Wr + (size_t)mode*H_*H_;
  const float* bias; float* C=nullptr; float alpha=1.f; const float* wsc=nullptr;
  switch(mode){
    case 0: bias=b_var; wsc=Wsc;    break;
    case 1: bias=b_sym; wsc=Wsc+H_; break;
    case 2: bias=b_q;   C=Qb; alpha=0.125f*LOG2E; break;
    default:bias=b_k;   C=Kb; break;
  }
  int tid=threadIdx.x, lane=tid&31, wid=tid>>5;
  int wr=wid&3, wc=wid>>2;
  int m0 = blockIdx.y*128, n0 = blockIdx.x*128;
  int sr = tid>>3, sq = (tid&7)*4;
  uint32_t smBase = (uint32_t)__cvta_generic_to_shared(sm);
  uint32_t sA0 = smBase + (sr*STP + sq)*4;
  uint32_t sA1 = sA0 + 128*STP*4;
  uint32_t sB0 = sA0 + 2*128*STP*4;
  uint32_t sB1 = sA0 + 3*128*STP*4;
  const float* gA = A + (size_t)(m0+sr)*H_ + sq;
  const float* gW = W + (size_t)(n0+sr)*H_ + sq;
  int mrow = wr*32 + (lane>>2), mc = 2*(lane&3);
  int brow = wc*64 + (lane>>2);
  const float* mA0 = sm + mrow*STP + mc;
  const float* mA1 = mA0 + 128*STP;
  const float* mB0 = sm + 2*128*STP + brow*STP + mc;
  const float* mB1 = mB0 + 128*STP;
  #define STAGE_P(sa, sb) do { \
    cpa16s((sa),            gA); \
    cpa16s((sa)+32*STP*4,   gA+32*H_); \
    cpa16s((sa)+64*STP*4,   gA+64*H_); \
    cpa16s((sa)+96*STP*4,   gA+96*H_); \
    cpa16s((sb),            gW); \
    cpa16s((sb)+32*STP*4,   gW+32*H_); \
    cpa16s((sb)+64*STP*4,   gW+64*H_); \
    cpa16s((sb)+96*STP*4,   gW+96*H_); \
    gA += KT; gW += KT; cp_commit(); } while(0)
  STAGE_P(sA0, sB0);
  float c[2][8][4];
  #pragma unroll
  for(int i=0;i<2;i++)
    #pragma unroll
    for(int j=0;j<8;j++){ c[i][j][0]=0;c[i][j][1]=0;c[i][j][2]=0;c[i][j][3]=0; }
  #pragma unroll 1
  for (int kt2=0; kt2<NKT/2; kt2++){
    cp_wait0(); __syncthreads();
    STAGE_P(sA1, sB1);
    mma_tile_pre<STP,8,4>(mA0, mB0, c);
    cp_wait0(); __syncthreads();
    if (kt2 < NKT/2-1) STAGE_P(sA0, sB0);
    mma_tile_pre<STP,8,4>(mA1, mB1, c);
  }
  #undef STAGE_P
  int t = lane&3;
  if (mode<=1){
    float p[4] = {0,0,0,0};
    #pragma unroll
    for (int rf=0; rf<2; rf++){
      #pragma unroll
      for (int nf=0; nf<8; nf++){
        int col0 = n0 + wc*64 + nf*8 + 2*t;
        float w0 = wsc[col0], w1 = wsc[col0+1];
        float b0v = bias[col0], b1v = bias[col0+1];
        p[rf*2+0] += ftanh(c[rf][nf][0]+b0v)*w0 + ftanh(c[rf][nf][1]+b1v)*w1;
        p[rf*2+1] += ftanh(c[rf][nf][2]+b0v)*w0 + ftanh(c[rf][nf][3]+b1v)*w1;
      }
    }
    #pragma unroll
    for (int i=0;i<4;i++){
      float v = p[i];
      v += __shfl_xor_sync(0xffffffffu, v, 1);
      v += __shfl_xor_sync(0xffffffffu, v, 2);
      if (t==0)
        atomicAdd(&g_sc[m0 + wr*32 + (i>>1)*16 + (lane>>2) + (i&1)*8], v);
    }
  } else {
    #pragma unroll
    for (int rf=0; rf<2; rf++){
      int row = m0 + wr*32 + rf*16 + (lane>>2);
      #pragma unroll
      for (int nf=0; nf<8; nf++){
        int col = n0 + wc*64 + nf*8;
        float b0v = bias[col + t], b1v = bias[col + t + 4];
        *(float2*)(C + (size_t)row*H_ + col + 2*t) =
          make_float2(tf32r(alpha*(c[rf][nf][0]+b0v)), tf32r(alpha*(c[rf][nf][1]+b1v)));
        *(float2*)(C + (size_t)(row+8)*H_ + col + 2*t) =
          make_float2(tf32r(alpha*(c[rf][nf][2]+b0v)), tf32r(alpha*(c[rf][nf][3]+b1v)));
      }
    }
  }
}

// ---------------- attention pass 1 ----------------
__global__ __launch_bounds__(256,2) void k_attn1(){
  extern __shared__ float sm[];
  int tid=threadIdx.x, lane=tid&31, wid=tid>>5;
  int wr=wid&3, wc=wid>>2;
  int bh=blockIdx.x, b=bh/NH_, h=bh-b*NH_;
  int n0=blockIdx.y*128;
  const float* Q = g_Qb + (size_t)b*N_*H_ + h*64;
  const float* K = g_Kb + (size_t)b*N_*H_ + h*64;
  int sr = tid>>4, sq = (tid&15)*4;
  uint32_t smBase = (uint32_t)__cvta_generic_to_shared(sm);
  uint32_t sQ  = smBase + (sr*ST + sq)*4;
  uint32_t sK0 = sQ + 128*ST*4;
  uint32_t sK1 = sQ + 2*128*ST*4;
  const float* gQ = Q + (size_t)(n0+sr)*H_ + sq;
  const float* gK = K + (size_t)sr*H_ + sq;
  int mrow = wr*32 + (lane>>2), mc = 2*(lane&3);
  int brow = wc*64 + (lane>>2);
  const float* mQ  = sm + mrow*ST + mc;
  const float* mK0 = sm + 128*ST + brow*ST + mc;
  const float* mK1 = mK0 + 128*ST;
  #define STAGE_A(sdst) do { \
    cpa16s((sdst),           gK); \
    cpa16s((sdst)+16*ST*4,   gK+16*H_); \
    cpa16s((sdst)+32*ST*4,   gK+32*H_); \
    cpa16s((sdst)+48*ST*4,   gK+48*H_); \
    cpa16s((sdst)+64*ST*4,   gK+64*H_); \
    cpa16s((sdst)+80*ST*4,   gK+80*H_); \
    cpa16s((sdst)+96*ST*4,   gK+96*H_); \
    cpa16s((sdst)+112*ST*4,  gK+112*H_); \
    gK += 128*H_; cp_commit(); } while(0)
  #pragma unroll
  for (int it=0; it<8; it++)
    cpa16s(sQ + it*16*ST*4, gQ + it*16*H_);
  STAGE_A(sK0);
  float z[4]={0,0,0,0};
  #pragma unroll 1
  for (int mt2=0; mt2<4; mt2++){
    cp_wait0(); __syncthreads();
    STAGE_A(sK1);
    {
      float c[2][8][4];
      #pragma unroll
      for(int i=0;i<2;i++)
        #pragma unroll
        for(int j=0;j<8;j++){ c[i][j][0]=0;c[i][j][1]=0;c[i][j][2]=0;c[i][j][3]=0; }
      mma_tile_pre<ST,8,8>(mQ, mK0, c);
      #pragma unroll
      for (int rf=0; rf<2; rf++)
        #pragma unroll
        for (int nf=0; nf<8; nf++){
          z[rf*2+0] += fex2(c[rf][nf][0]) + fex2(c[rf][nf][1]);
          z[rf*2+1] += fex2(c[rf][nf][2]) + fex2(c[rf][nf][3]);
        }
    }
    cp_wait0(); __syncthreads();
    if (mt2 < 3) STAGE_A(sK0);
    {
      float c[2][8][4];
      #pragma unroll
      for(int i=0;i<2;i++)
        #pragma unroll
        for(int j=0;j<8;j++){ c[i][j][0]=0;c[i][j][1]=0;c[i][j][2]=0;c[i][j][3]=0; }
      mma_tile_pre<ST,8,8>(mQ, mK1, c);
      #pragma unroll
      for (int rf=0; rf<2; rf++)
        #pragma unroll
        for (int nf=0; nf<8; nf++){
          z[rf*2+0] += fex2(c[rf][nf][0]) + fex2(c[rf][nf][1]);
          z[rf*2+1] += fex2(c[rf][nf][2]) + fex2(c[rf][nf][3]);
        }
    }
  }
  #undef STAGE_A
  #pragma unroll
  for (int i=0;i<4;i++){
    float v = z[i];
    v += __shfl_xor_sync(0xffffffffu, v, 1);
    v += __shfl_xor_sync(0xffffffffu, v, 2);
    if ((lane&3)==0)
      atomicAdd(&g_Z[(size_t)bh*N_ + n0 + wr*32 + (i>>1)*16 + (lane>>2) + (i&1)*8], v);
  }
}

// ---------------- cross scores ----------------
__global__ __launch_bounds__(128) void k_cross(const float* __restrict__ x, const float* __restrict__ Wc,
                                               const float* __restrict__ bc, const int* __restrict__ occ){
  int pid = blockIdx.x;
  int b = pid / M_;
  int o0 = occ[pid*2], o1 = occ[pid*2+1];
  const float* x0 = x + ((size_t)b*N_+o0)*H_;
  const float* x1 = x + ((size_t)b*N_+o1)*H_;
  float p = 0.f;
  for (int h=threadIdx.x; h<H_; h+=128) p += 0.5f*(x0[h]+x1[h])*Wc[h];
  for (int o=16;o;o>>=1) p += __shfl_xor_sync(0xffffffffu, p, o);
  __shared__ float red[4];
  if ((threadIdx.x&31)==0) red[threadIdx.x>>5] = p;
  __syncthreads();
  if (threadIdx.x==0){
    float t = d_lrelu(bc[0] + red[0]+red[1]+red[2]+red[3]);
    atomicAdd(&g_vg2[b*N_+o0], t*t);
    atomicAdd(&g_vg2[b*N_+o1], t*t);
  }
}

// ---------------- band + sumw + coef + c-sums ----------------
__global__ __launch_bounds__(1024) void k_post(const int* __restrict__ pp){
  __shared__ float ab[N_], wt[N_], red[32], red2[32];
  __shared__ float swv;
  int b = blockIdx.x, n = threadIdx.x;
  const int* P = pp + b*N_;
  const float* s = g_sc + b*N_;
  float a = 0.f;
  if (n < N_-1){
    float sl1 = d_pred(P,n+1) ? d_lrelu(s[n+1]) : 0.f;
    bool up0 = d_pred(P,n) && (n<=1 || !d_single(P,n));
    float su0 = up0 ? d_lrelu(s[n]) : 0.f;
    a = sl1 + su0;
  }
  ab[n] = a; g_ab[b*N_+n] = a;
  bool up = d_pred(P,n) && (n<=1 || !d_single(P,n));
  bool tr = up && (n>=1);
  float w = d_pred(P,n) ? (tr?3.f:2.f) : 0.f;
  wt[n] = w;
  float v = w;
  for (int o=16;o;o>>=1) v += __shfl_xor_sync(0xffffffffu, v, o);
  if ((n&31)==0) red[n>>5] = v;
  __syncthreads();
  if (n < 32){
    float t2 = red[n];
    for (int o=16;o;o>>=1) t2 += __shfl_xor_sync(0xffffffffu, t2, o);
    if (n==0) swv = t2;
  }
  __syncthreads();
  float am1 = (n>=1) ? ab[n-1] : 0.f;
  g_dg[b*N_+n] = 0.8f*(am1*am1 + a*a) + g_vg2[b*N_+n];
  float sw = swv;
  int nm = (n+N_-1)&(N_-1), np = (n+1)&(N_-1);
  float c1 = (wt[nm]*(d_single(P,nm)?1.f:0.5f) + wt[np]*(d_single(P,np)?0.f:0.5f)) / sw;
  float c2 = wt[n] / sw;
  g_c1[b*N_+n] = c1;
  g_c2[b*N_+n] = c2;
  // reduce c-sums
  float v1 = c1, v2 = c2;
  for (int o=16;o;o>>=1){
    v1 += __shfl_xor_sync(0xffffffffu, v1, o);
    v2 += __shfl_xor_sync(0xffffffffu, v2, o);
  }
  __syncthreads();
  if ((n&31)==0){ red[n>>5] = v1; red2[n>>5] = v2; }
  __syncthreads();
  if (n < 32){
    float t1 = red[n], t2 = red2[n];
    for (int o=16;o;o>>=1){
      t1 += __shfl_xor_sync(0xffffffffu, t1, o);
      t2 += __shfl_xor_sync(0xffffffffu, t2, o);
    }
    if (n==0){ g_cs1[b] = t1; g_cs2[b] = t2; }
  }
}

// ---------------- band correction ----------------
__global__ __launch_bounds__(256) void k_bandfix(){
  int bh = blockIdx.x, b = bh/NH_, h = bh - b*NH_;
  int wid = threadIdx.x>>5, lane = threadIdx.x&31;
  int n = blockIdx.y*8 + wid;
  const float* Qr = g_Qb + ((size_t)b*N_ + n)*H_ + h*64;
  const float* Kp = g_Kb + (size_t)b*N_*H_ + h*64;
  const float* ab = g_ab + b*N_;
  float q0 = Qr[lane], q1 = Qr[lane+32];
  float anm2=(n>=2)?ab[n-2]:0.f, anm1=(n>=1)?ab[n-1]:0.f;
  float an=ab[n], anp1=(n<N_-1)?ab[n+1]:0.f;
  float biasv[5] = { LOG2E*0.8f*anm2*anm1, LOG2E*0.2f*anm1, LOG2E*g_dg[b*N_+n],
                     LOG2E*0.2f*an, LOG2E*0.8f*an*anp1 };
  float delta[5];
  float dz = 0.f;
  #pragma unroll
  for (int d=-2; d<=2; d++){
    int m = n + d;
    delta[d+2] = 0.f;
    if ((unsigned)m < (unsigned)N_){
      const float* Kr = Kp + (size_t)m*H_;
      float s = q0*Kr[lane] + q1*Kr[lane+32];
      #pragma unroll
      for (int o=16;o;o>>=1) s += __shfl_xor_sync(0xffffffffu, s, o);
      delta[d+2] = fex2(s + biasv[d+2]) - fex2(s);
      dz += delta[d+2];
    }
  }
  float Zf = g_Z[(size_t)bh*N_ + n] + dz;
  if (lane==0) g_Z[(size_t)bh*N_ + n] = Zf;
  float w1 = g_c1[b*N_+n] / Zf;
  float w2 = g_c2[b*N_+n] / Zf;
  if (lane==0 && (w1 != 0.f || w2 != 0.f)){
    #pragma unroll
    for (int d=-2; d<=2; d++){
      int m = n + d;
      if ((unsigned)m < (unsigned)N_ && delta[d+2] != 0.f){
        atomicAdd(&g_r1[(size_t)bh*N_ + m], w1*delta[d+2]);
        atomicAdd(&g_r2[(size_t)bh*N_ + m], w2*delta[d+2]);
      }
    }
  }
}

// ---------------- attention pass 2 ----------------
__global__ __launch_bounds__(256,2) void k_attn2(){
  extern __shared__ float sm[];
  float* colp = sm + 3*128*ST;
  int tid=threadIdx.x, lane=tid&31, wid=tid>>5;
  int wr=wid&3, wc=wid>>2;
  int bh=blockIdx.x, b=bh/NH_, h=bh-b*NH_;
  int m0=blockIdx.y*128;
  const float* Q = g_Qb + (size_t)b*N_*H_ + h*64;
  const float* K = g_Kb + (size_t)b*N_*H_ + h*64;
  int sr = tid>>4, sq = (tid&15)*4;
  uint32_t smBase = (uint32_t)__cvta_generic_to_shared(sm);
  uint32_t sKr = smBase + (sr*ST + sq)*4;
  uint32_t sQ0 = sKr + 128*ST*4;
  uint32_t sQ1 = sKr + 2*128*ST*4;
  const float* gKr = K + (size_t)(m0+sr)*H_ + sq;
  const float* gQ  = Q + (size_t)sr*H_ + sq;
  int mrow = wr*32 + (lane>>2), mc = 2*(lane&3);
  int brow = wc*64 + (lane>>2);
  const float* mK  = sm + mrow*ST + mc;
  const float* mQ0 = sm + 128*ST + brow*ST + mc;
  const float* mQ1 = mQ0 + 128*ST;
  int nctr = 0;
  #define STAGE_Q(sdst, cbuf) do { \
    cpa16s((sdst),           gQ); \
    cpa16s((sdst)+16*ST*4,   gQ+16*H_); \
    cpa16s((sdst)+32*ST*4,   gQ+32*H_); \
    cpa16s((sdst)+48*ST*4,   gQ+48*H_); \
    cpa16s((sdst)+64*ST*4,   gQ+64*H_); \
    cpa16s((sdst)+80*ST*4,   gQ+80*H_); \
    cpa16s((sdst)+96*ST*4,   gQ+96*H_); \
    cpa16s((sdst)+112*ST*4,  gQ+112*H_); \
    gQ += 128*H_; \
    if (tid < 128){ \
      int n = nctr*128 + tid; \
      float iz = 1.f / g_Z[(size_t)bh*N_ + n]; \
      colp[(cbuf)*256 + tid]       = g_c1[b*N_+n]*iz; \
      colp[(cbuf)*256 + 128 + tid] = g_c2[b*N_+n]*iz; \
    } \
    nctr++; cp_commit(); } while(0)
  #pragma unroll
  for (int it=0; it<8; it++)
    cpa16s(sKr + it*16*ST*4, gKr + it*16*H_);
  STAGE_Q(sQ0, 0);
  float r1[4]={0,0,0,0}, r2[4]={0,0,0,0};
  #pragma unroll 1
  for (int nt2=0; nt2<4; nt2++){
    cp_wait0(); __syncthreads();
    STAGE_Q(sQ1, 1);
    {
      float c[2][8][4];
      #pragma unroll
      for(int i=0;i<2;i++)
        #pragma unroll
        for(int j=0;j<8;j++){ c[i][j][0]=0;c[i][j][1]=0;c[i][j][2]=0;c[i][j][3]=0; }
      mma_tile_pre<ST,8,8>(mK, mQ0, c);
      const float* cp0 = colp;
      #pragma unroll
      for (int rf=0; rf<2; rf++)
        #pragma unroll
        for (int nf=0; nf<8; nf++){
          int lc0 = wc*64 + nf*8 + 2*(lane&3);
          float w1a = cp0[lc0], w1b = cp0[lc0+1];
          float w2a = cp0[128+lc0], w2b = cp0[128+lc0+1];
          float P0 = fex2(c[rf][nf][0]), P1 = fex2(c[rf][nf][1]);
          float P2 = fex2(c[rf][nf][2]), P3 = fex2(c[rf][nf][3]);
          r1[rf*2+0] += w1a*P0 + w1b*P1;  r2[rf*2+0] += w2a*P0 + w2b*P1;
          r1[rf*2+1] += w1a*P2 + w1b*P3;  r2[rf*2+1] += w2a*P2 + w2b*P3;
        }
    }
    cp_wait0(); __syncthreads();
    if (nt2 < 3) STAGE_Q(sQ0, 0);
    {
      float c[2][8][4];
      #pragma unroll
      for(int i=0;i<2;i++)
        #pragma unroll
        for(int j=0;j<8;j++){ c[i][j][0]=0;c[i][j][1]=0;c[i][j][2]=0;c[i][j][3]=0; }
      mma_tile_pre<ST,8,8>(mK, mQ1, c);
      const float* cp0 = colp + 256;
      #pragma unroll
      for (int rf=0; rf<2; rf++)
        #pragma unroll
        for (int nf=0; nf<8; nf++){
          int lc0 = wc*64 + nf*8 + 2*(lane&3);
          float w1a = cp0[lc0], w1b = cp0[lc0+1];
          float w2a = cp0[128+lc0], w2b = cp0[128+lc0+1];
          float P0 = fex2(c[rf][nf][0]), P1 = fex2(c[rf][nf][1]);
          float P2 = fex2(c[rf][nf][2]), P3 = fex2(c[rf][nf][3]);
          r1[rf*2+0] += w1a*P0 + w1b*P1;  r2[rf*2+0] += w2a*P0 + w2b*P1;
          r1[rf*2+1] += w1a*P2 + w1b*P3;  r2[rf*2+1] += w2a*P2 + w2b*P3;
        }
    }
  }
  #undef STAGE_Q
  #pragma unroll
  for (int i=0;i<4;i++){
    float v1 = r1[i], v2 = r2[i];
    v1 += __shfl_xor_sync(0xffffffffu, v1, 1);
    v1 += __shfl_xor_sync(0xffffffffu, v1, 2);
    v2 += __shfl_xor_sync(0xffffffffu, v2, 1);
    v2 += __shfl_xor_sync(0xffffffffu, v2, 2);
    if ((lane&3)==0){
      size_t o = (size_t)bh*N_ + m0 + wr*32 + (i>>1)*16 + (lane>>2) + (i&1)*8;
      atomicAdd(&g_r1[o], v1);
      atomicAdd(&g_r2[o], v2);
    }
  }
}

// ---------------- y = r @ x  (replaces r @ V; V-projection eliminated) ----------------
__global__ __launch_bounds__(256) void k_ry(const float* __restrict__ x){
  __shared__ __align__(16) float rs1[256][12], rs2[256][12];
  int b = blockIdx.x;
  int k = blockIdx.y*256 + threadIdx.x;
  int m0 = blockIdx.z*256;
  int tid = threadIdx.x;
  // stage r chunk: [m][h]
  for (int idx = tid; idx < 12*256; idx += 256){
    int h = idx >> 8, m = idx & 255;
    rs1[m][h] = g_r1[((size_t)(b*NH_+h))*N_ + m0 + m];
    rs2[m][h] = g_r2[((size_t)(b*NH_+h))*N_ + m0 + m];
  }
  __syncthreads();
  float y1[12] = {0,0,0,0,0,0,0,0,0,0,0,0};
  float y2[12] = {0,0,0,0,0,0,0,0,0,0,0,0};
  const float* xp = x + ((size_t)(b<<10) + m0)*H_ + k;
  #pragma unroll 4
  for (int m=0; m<256; m++){
    float xv = xp[(size_t)m*H_];
    float4 a0 = *(const float4*)&rs1[m][0];
    float4 a1 = *(const float4*)&rs1[m][4];
    float4 a2 = *(const float4*)&rs1[m][8];
    float4 b0 = *(const float4*)&rs2[m][0];
    float4 b1 = *(const float4*)&rs2[m][4];
    float4 b2 = *(const float4*)&rs2[m][8];
    y1[0]+=a0.x*xv; y1[1]+=a0.y*xv; y1[2]+=a0.z*xv; y1[3]+=a0.w*xv;
    y1[4]+=a1.x*xv; y1[5]+=a1.y*xv; y1[6]+=a1.z*xv; y1[7]+=a1.w*xv;
    y1[8]+=a2.x*xv; y1[9]+=a2.y*xv; y1[10]+=a2.z*xv; y1[11]+=a2.w*xv;
    y2[0]+=b0.x*xv; y2[1]+=b0.y*xv; y2[2]+=b0.z*xv; y2[3]+=b0.w*xv;
    y2[4]+=b1.x*xv; y2[5]+=b1.y*xv; y2[6]+=b1.z*xv; y2[7]+=b1.w*xv;
    y2[8]+=b2.x*xv; y2[9]+=b2.y*xv; y2[10]+=b2.z*xv; y2[11]+=b2.w*xv;
  }
  #pragma unroll
  for (int h=0; h<12; h++){
    atomicAdd(&g_y1[((size_t)(b*NH_+h))*H_ + k], y1[h]);
    atomicAdd(&g_y2[((size_t)(b*NH_+h))*H_ + k], y2[h]);
  }
}

// ---------------- A = y @ Wv^T + bv * cs  (fp32) ----------------
__global__ __launch_bounds__(256) void k_final0(const float* __restrict__ Wv, const float* __restrict__ bv){
  int b = blockIdx.x, tile = blockIdx.y;
  int tid = threadIdx.x, lane = tid&31, w = tid>>5;
  float cs1 = g_cs1[b], cs2 = g_cs2[b];
  #pragma unroll 1
  for (int oo=0; oo<16; oo++){
    int o = tile*128 + w*16 + oo;
    int h = o >> 6;
    const float* wv = Wv + (size_t)o*H_;
    const float* y1p = g_y1 + ((size_t)(b*NH_+h))*H_;
    const float* y2p = g_y2 + ((size_t)(b*NH_+h))*H_;
    float u1=0.f, u2=0.f;
    #pragma unroll
    for (int kk=0; kk<H_/32; kk++){
      float wvv = wv[lane + kk*32];
      u1 += wvv*y1p[lane + kk*32];
      u2 += wvv*y2p[lane + kk*32];
    }
    #pragma unroll
    for (int off=16; off; off>>=1){
      u1 += __shfl_xor_sync(0xffffffffu, u1, off);
      u2 += __shfl_xor_sync(0xffffffffu, u2, off);
    }
    if (lane==0){
      g_A1[b*H_+o] = u1 + bv[o]*cs1;
      g_A2[b*H_+o] = u2 + bv[o]*cs2;
    }
  }
}

// ---------------- final GEMVs ----------------
__global__ __launch_bounds__(256) void k_final1(const float* __restrict__ Wo, const float* __restrict__ bo){
  __shared__ float A1s[H_], A2s[H_];
  int b = blockIdx.x, tile = blockIdx.y;
  int tid = threadIdx.x, lane = tid&31, w = tid>>5;
  for (int i=tid; i<H_; i+=256){ A1s[i]=g_A1[b*H_+i]; A2s[i]=g_A2[b*H_+i]; }
  __syncthreads();
  #pragma unroll 1
  for (int oo=0; oo<16; oo++){
    int o = tile*128 + w*16 + oo;
    const float* wr = Wo + (size_t)o*H_;
    float u1=0.f, u2=0.f;
    #pragma unroll
    for (int k=0; k<H_/32; k++){
      float wv = wr[lane + k*32];
      u1 += wv*A1s[lane + k*32];
      u2 += wv*A2s[lane + k*32];
    }
    #pragma unroll
    for (int off=16; off; off>>=1){
      u1 += __shfl_xor_sync(0xffffffffu, u1, off);
      u2 += __shfl_xor_sync(0xffffffffu, u2, off);
    }
    if (lane==0){
      g_u1[b*H_+o] = u1 + bo[o];
      g_u2[b*H_+o] = u2 + bo[o];
    }
  }
}

__global__ __launch_bounds__(256) void k_final2(const float* __restrict__ Wa, const float* __restrict__ ba,
                                                float* __restrict__ out){
  __shared__ float u1s[H_], u2s[H_], pms[128];
  int b = blockIdx.x, tile = blockIdx.y;
  int tid = threadIdx.x, lane = tid&31, w = tid>>5;
  for (int i=tid; i<H_; i+=256){ u1s[i]=g_u1[b*H_+i]; u2s[i]=g_u2[b*H_+i]; }
  __syncthreads();
  #pragma unroll 1
  for (int oo=0; oo<16; oo++){
    int o = tile*128 + w*16 + oo;
    const float* wa = Wa + (size_t)o*2*H_;
    float p = 0.f;
    #pragma unroll
    for (int k=0; k<H_/32; k++){
      p += wa[lane + k*32]*u1s[lane + k*32];
      p += wa[H_ + lane + k*32]*u2s[lane + k*32];
    }
    #pragma unroll
    for (int off=16; off; off>>=1)
      p += __shfl_xor_sync(0xffffffffu, p, off);
    if (lane==0) pms[w*16 + oo] = p + ba[o];
  }
  __syncthreads();
  int f0 = tile*128;
  float4 v0 = *(float4*)(pms + (tid&31)*4);
  int rowstart = tid>>5;
  for (int n = rowstart; n < N_; n += 8){
    *(float4*)(out + ((size_t)b*N_ + n)*H_ + f0 + (tid&31)*4) = v0;
  }
}

// ---------------- launch ----------------
extern "C" void kernel_launch(void* const* d_in, const int* in_sizes, int n_in,
                              void* d_out, int out_size){
  (void)in_sizes; (void)n_in; (void)out_size;
  const float* x      = (const float*)d_in[0];
  const float* W_var  = (const float*)d_in[3];
  const float* b_var  = (const float*)d_in[4];
  const float* W_sym  = (const float*)d_in[5];
  const float* b_sym  = (const float*)d_in[6];
  const float* W_sc   = (const float*)d_in[7];
  const float* b_scb  = (const float*)d_in[8];
  const float* W_cr   = (const float*)d_in[9];
  const float* b_cr   = (const float*)d_in[10];
  const float* W_atom = (const float*)d_in[11];
  const float* b_atom = (const float*)d_in[12];
  const float* W_q    = (const float*)d_in[13];
  const float* b_q    = (const float*)d_in[14];
  const float* W_k    = (const float*)d_in[15];
  const float* b_k    = (const float*)d_in[16];
  const float* W_v    = (const float*)d_in[17];
  const float* b_v    = (const float*)d_in[18];
  const float* W_o    = (const float*)d_in[19];
  const float* b_o    = (const float*)d_in[20];
  const int*   pp     = (const int*)d_in[21];
  const int*   occ    = (const int*)d_in[24];
  float* out = (float*)d_out;

  float *p_Q, *p_K;
  cudaGetSymbolAddress((void**)&p_Q, g_Qb);
  cudaGetSymbolAddress((void**)&p_K, g_Kb);

  const int PROJ_SMEM  = (4*128*STP)*4;
  const int ATTN1_SMEM = (3*128*ST)*4;
  const int ATTN2_SMEM = (3*128*ST + 512)*4;
  static bool attr_done = false;
  static cudaStream_t s2 = nullptr;
  static cudaEvent_t eF = nullptr, eJ = nullptr;
  if (!attr_done){
    cudaFuncSetAttribute(k_proj,  cudaFuncAttributeMaxDynamicSharedMemorySize, PROJ_SMEM);
    cudaFuncSetAttribute(k_attn1, cudaFuncAttributeMaxDynamicSharedMemorySize, ATTN1_SMEM);
    cudaFuncSetAttribute(k_attn2, cudaFuncAttributeMaxDynamicSharedMemorySize, ATTN2_SMEM);
    cudaStreamCreateWithFlags(&s2, cudaStreamNonBlocking);
    cudaEventCreateWithFlags(&eF, cudaEventDisableTiming);
    cudaEventCreateWithFlags(&eJ, cudaEventDisableTiming);
    attr_done = true;
  }

  k_init<<<(B_*NH_*N_+255)/256, 256>>>(b_scb);                                   // 1
  const int PRE = 2*(B_*N_*H_/8) + 4*(H_*H_/8);
  k_preconv<<<(PRE+255)/256, 256>>>(x, pp, W_var, W_sym, W_q, W_k);              // 2
  cudaEventRecord(eF, 0);
  cudaStreamWaitEvent(s2, eF, 0);
  dim3 gpQK(H_/128, (B_*N_)/128, 2);
  k_proj<<<gpQK, 256, PROJ_SMEM>>>(b_var, b_sym, b_q, b_k, W_sc, p_Q, p_K, 0);   // 3
  dim3 ga(B_*NH_, N_/128);
  k_attn1<<<ga, 256, ATTN1_SMEM>>>();                                            // 4 <- profiled
  // side stream: score projections + cross + post (independent of Q/K/attn1)
  dim3 gpS(H_/128, (B_*N_)/128, 2);
  k_proj<<<gpS, 256, PROJ_SMEM, s2>>>(b_var, b_sym, b_q, b_k, W_sc, p_Q, p_K, 1);
  k_cross<<<B_*M_, 128, 0, s2>>>(x, W_cr, b_cr, occ);
  k_post<<<B_, 1024, 0, s2>>>(pp);
  cudaEventRecord(eJ, s2);
  cudaStreamWaitEvent(0, eJ, 0);
  dim3 gbf(B_*NH_, N_/8);
  k_bandfix<<<gbf, 256>>>();
  k_attn2<<<ga, 256, ATTN2_SMEM>>>();
  dim3 gry(B_, H_/256, N_/256);
  k_ry<<<gry, 256>>>(x);
  dim3 gf(B_, H_/128);
  k_final0<<<gf, 256>>>(W_v, b_v);
  k_final1<<<gf, 256>>>(W_o, b_o);
  k_final2<<<gf, 256>>>(W_atom, b_atom, out);
}

// round 17
// speedup vs baseline: 1.2032x; 1.2032x over previous
#include <cuda_runtime.h>
#include <mma.h>
#include <cstdint>
using namespace nvcuda;

#define B_ 8
#define N_ 1024
#define H_ 768
#define NH_ 12
#define M_ 256
#define ST 72
#define STP 40
#define KT 32
#define NKT 24
#define LOG2E 1.4426950408889634f

// ---------------- scratch ----------------
__device__ float g_xr[B_*N_*H_];
__device__ float g_vi[B_*N_*H_];
__device__ float g_Wr[5*H_*H_];
__device__ float g_Qb[B_*N_*H_];
__device__ float g_Kb[B_*N_*H_];
__device__ float g_Vb[B_*N_*H_];
__device__ float g_sc[B_*N_];
__device__ float g_vg2[B_*N_];
__device__ float g_ab[B_*N_];
__device__ float g_dg[B_*N_];
__device__ float g_c1[B_*N_];
__device__ float g_c2[B_*N_];
__device__ int   g_pcnt[B_];
__device__ int   g_pidx[B_*N_];
__device__ float g_Z[B_*NH_*N_];
__device__ float g_r1[B_*NH_*N_];
__device__ float g_r2[B_*NH_*N_];
__device__ float g_A1[B_*H_];
__device__ float g_A2[B_*H_];
__device__ float g_u1[B_*H_];
__device__ float g_u2[B_*H_];

__device__ __forceinline__ bool d_pred(const int* P, int i){ return P[i]==1; }
__device__ __forceinline__ bool d_single(const int* P, int i){ return (i==0) || (i>=2 && P[i-2]==1); }
__device__ __forceinline__ float d_lrelu(float t){ return t >= 0.f ? t : 0.02f*t; }
__device__ __forceinline__ float tf32r(float x){ return wmma::__float_to_tf32(x); }
__device__ __forceinline__ float fex2(float x){ float y; asm("ex2.approx.f32 %0, %1;" : "=f"(y) : "f"(x)); return y; }
__device__ __forceinline__ float ftanh(float x){ float y; asm("tanh.approx.f32 %0, %1;" : "=f"(y) : "f"(x)); return y; }

__device__ __forceinline__ void perm_store(float* dst, float4 a, float4 b){
  float4 o0 = make_float4(tf32r(a.x), tf32r(b.x), tf32r(a.y), tf32r(b.y));
  float4 o1 = make_float4(tf32r(a.z), tf32r(b.z), tf32r(a.w), tf32r(b.w));
  *(float4*)dst = o0; *(float4*)(dst+4) = o1;
}

// ---------------- cp.async ----------------
__device__ __forceinline__ void cpa16s(uint32_t s, const float* g){
  asm volatile("cp.async.cg.shared.global [%0], [%1], 16;\n" :: "r"(s), "l"(g));
}
__device__ __forceinline__ void cp_commit(){ asm volatile("cp.async.commit_group;\n"); }
__device__ __forceinline__ void cp_wait0(){ asm volatile("cp.async.wait_group 0;\n"); }

// ---------------- m16n8k8 tf32 mma.sync ----------------
__device__ __forceinline__ void mma8(float c[4], const uint32_t a[4], uint32_t b0, uint32_t b1){
  asm volatile(
    "mma.sync.aligned.m16n8k8.row.col.f32.tf32.tf32.f32 "
    "{%0,%1,%2,%3}, {%4,%5,%6,%7}, {%8,%9}, {%0,%1,%2,%3};\n"
    : "+f"(c[0]), "+f"(c[1]), "+f"(c[2]), "+f"(c[3])
    : "r"(a[0]), "r"(a[1]), "r"(a[2]), "r"(a[3]), "r"(b0), "r"(b1));
}

template<int STRIDE, int NF, int K8>
__device__ __forceinline__ void mma_tile_pre(const float* __restrict__ mA,
                                             const float* __restrict__ mB,
                                             float c[2][NF][4]){
  #pragma unroll
  for (int k8=0;k8<K8;k8++){
    uint32_t a[2][4];
    #pragma unroll
    for (int rf=0; rf<2; rf++){
      float2 v0 = *(const float2*)(mA + rf*16*STRIDE + k8*8);
      float2 v1 = *(const float2*)(mA + rf*16*STRIDE + 8*STRIDE + k8*8);
      a[rf][0]=__float_as_uint(v0.x); a[rf][2]=__float_as_uint(v0.y);
      a[rf][1]=__float_as_uint(v1.x); a[rf][3]=__float_as_uint(v1.y);
    }
    #pragma unroll
    for (int nf=0;nf<NF;nf++){
      float2 bv = *(const float2*)(mB + nf*8*STRIDE + k8*8);
      mma8(c[0][nf], a[0], __float_as_uint(bv.x), __float_as_uint(bv.y));
      mma8(c[1][nf], a[1], __float_as_uint(bv.x), __float_as_uint(bv.y));
    }
  }
}

// ---------------- init ----------------
__global__ void k_init(const float* __restrict__ bsc){
  int i = blockIdx.x*blockDim.x + threadIdx.x;
  if (i < B_*N_){ g_vg2[i] = 0.f; g_sc[i] = bsc[0]; }
  if (i < B_){ g_pcnt[i] = 0; }
  if (i < B_*H_){ g_A1[i]=0.f; g_A2[i]=0.f; }
  if (i < B_*NH_*N_){ g_Z[i]=0.f; g_r1[i]=0.f; g_r2[i]=0.f; }
}

// ---------------- predicate list ----------------
__global__ __launch_bounds__(1024) void k_plist(const int* __restrict__ pp){
  int b = blockIdx.x, n = threadIdx.x;
  if (pp[b*N_+n] == 1){
    int j = atomicAdd(&g_pcnt[b], 1);
    g_pidx[b*N_+j] = n;
  }
}

// ---------------- preconv (x, var_in, 5 weights) ----------------
__global__ void k_preconv(const float* __restrict__ x, const int* __restrict__ pp,
                          const float* __restrict__ W0, const float* __restrict__ W1,
                          const float* __restrict__ W2, const float* __restrict__ W3,
                          const float* __restrict__ W4){
  const int XT8 = B_*N_*H_/8;
  const int WT8 = H_*H_/8;
  const int H8 = H_/8;
  int i = blockIdx.x*blockDim.x + threadIdx.x;
  if (i < XT8){
    const float4* s = (const float4*)x + (size_t)i*2;
    perm_store(g_xr + (size_t)i*8, s[0], s[1]);
  } else if (i < 2*XT8){
    int j = i - XT8;
    int hh8 = j % H8;
    int nn  = (j / H8) % N_;
    int b   = j / (N_*H8);
    bool single = (nn==0) || (nn>=2 && pp[b*N_+nn-2]==1);
    int np = (nn+1)&(N_-1), nm = (nn+N_-1)&(N_-1);
    const float* bp = x + ((size_t)b*N_ + np)*H_ + hh8*8;
    float4 xa = *(const float4*)bp, xb = *(const float4*)(bp+4);
    if (!single){
      const float* bm = x + ((size_t)b*N_ + nm)*H_ + hh8*8;
      float4 ya = *(const float4*)bm, yb = *(const float4*)(bm+4);
      xa.x=0.5f*(xa.x+ya.x); xa.y=0.5f*(xa.y+ya.y); xa.z=0.5f*(xa.z+ya.z); xa.w=0.5f*(xa.w+ya.w);
      xb.x=0.5f*(xb.x+yb.x); xb.y=0.5f*(xb.y+yb.y); xb.z=0.5f*(xb.z+yb.z); xb.w=0.5f*(xb.w+yb.w);
    }
    perm_store(g_vi + (size_t)j*8, xa, xb);
  } else {
    int j = i - 2*XT8;
    if (j < 5*WT8){
      int w = j / WT8, o = j - w*WT8;
      int row = o / H8, rem = o - row*H8;
      int srow = row;
      if (w==2 || w==3){
        int r8 = row & 7;
        srow = (row & ~7) | ((r8&1)*4 + (r8>>1));
      }
      const float* src = (w==0)?W0:(w==1)?W1:(w==2)?W2:(w==3)?W3:W4;
      const float4* s = (const float4*)(src + (size_t)srow*H_ + rem*8);
      perm_store(g_Wr + (size_t)w*H_*H_ + (size_t)o*8, s[0], s[1]);
    }
  }
}

// ---------------- projections: sel=0 -> modes {2,3} (Q,K); sel=1 -> mode 4 (V) ----------------
__global__ __launch_bounds__(256,2) void k_proj(
    const float* __restrict__ b_q, const float* __restrict__ b_k, const float* __restrict__ b_v,
    float* __restrict__ Qb, float* __restrict__ Kb, float* __restrict__ Vb, int sel){
  extern __shared__ float sm[];
  int mode = sel ? 4 : (blockIdx.z+2);
  const float* A = g_xr;
  const float* W = g_Wr + (size_t)mode*H_*H_;
  const float* bias; float* C; float alpha=1.f;
  switch(mode){
    case 2: bias=b_q; C=Qb; alpha=0.125f*LOG2E; break;
    case 3: bias=b_k; C=Kb; break;
    default:bias=b_v; C=Vb; break;
  }
  int tid=threadIdx.x, lane=tid&31, wid=tid>>5;
  int wr=wid&3, wc=wid>>2;
  int m0 = blockIdx.y*128, n0 = blockIdx.x*128;
  int sr = tid>>3, sq = (tid&7)*4;
  uint32_t smBase = (uint32_t)__cvta_generic_to_shared(sm);
  uint32_t sA0 = smBase + (sr*STP + sq)*4;
  uint32_t sA1 = sA0 + 128*STP*4;
  uint32_t sB0 = sA0 + 2*128*STP*4;
  uint32_t sB1 = sA0 + 3*128*STP*4;
  const float* gA = A + (size_t)(m0+sr)*H_ + sq;
  const float* gW = W + (size_t)(n0+sr)*H_ + sq;
  int mrow = wr*32 + (lane>>2), mc = 2*(lane&3);
  int brow = wc*64 + (lane>>2);
  const float* mA0 = sm + mrow*STP + mc;
  const float* mA1 = mA0 + 128*STP;
  const float* mB0 = sm + 2*128*STP + brow*STP + mc;
  const float* mB1 = mB0 + 128*STP;
  #define STAGE_P(sa, sb) do { \
    cpa16s((sa),            gA); \
    cpa16s((sa)+32*STP*4,   gA+32*H_); \
    cpa16s((sa)+64*STP*4,   gA+64*H_); \
    cpa16s((sa)+96*STP*4,   gA+96*H_); \
    cpa16s((sb),            gW); \
    cpa16s((sb)+32*STP*4,   gW+32*H_); \
    cpa16s((sb)+64*STP*4,   gW+64*H_); \
    cpa16s((sb)+96*STP*4,   gW+96*H_); \
    gA += KT; gW += KT; cp_commit(); } while(0)
  STAGE_P(sA0, sB0);
  float c[2][8][4];
  #pragma unroll
  for(int i=0;i<2;i++)
    #pragma unroll
    for(int j=0;j<8;j++){ c[i][j][0]=0;c[i][j][1]=0;c[i][j][2]=0;c[i][j][3]=0; }
  #pragma unroll 1
  for (int kt2=0; kt2<NKT/2; kt2++){
    cp_wait0(); __syncthreads();
    STAGE_P(sA1, sB1);
    mma_tile_pre<STP,8,4>(mA0, mB0, c);
    cp_wait0(); __syncthreads();
    if (kt2 < NKT/2-1) STAGE_P(sA0, sB0);
    mma_tile_pre<STP,8,4>(mA1, mB1, c);
  }
  #undef STAGE_P
  int t = lane&3;
  if (mode==4){
    #pragma unroll
    for (int rf=0; rf<2; rf++){
      int row = m0 + wr*32 + rf*16 + (lane>>2);
      #pragma unroll
      for (int nf=0; nf<8; nf++){
        int col0 = n0 + wc*64 + nf*8 + 2*t;
        float2 bv = *(const float2*)(bias + col0);
        *(float2*)(C + (size_t)row*H_ + col0)     = make_float2(c[rf][nf][0]+bv.x, c[rf][nf][1]+bv.y);
        *(float2*)(C + (size_t)(row+8)*H_ + col0) = make_float2(c[rf][nf][2]+bv.x, c[rf][nf][3]+bv.y);
      }
    }
  } else {
    #pragma unroll
    for (int rf=0; rf<2; rf++){
      int row = m0 + wr*32 + rf*16 + (lane>>2);
      #pragma unroll
      for (int nf=0; nf<8; nf++){
        int col = n0 + wc*64 + nf*8;
        float b0v = bias[col + t], b1v = bias[col + t + 4];
        *(float2*)(C + (size_t)row*H_ + col + 2*t) =
          make_float2(tf32r(alpha*(c[rf][nf][0]+b0v)), tf32r(alpha*(c[rf][nf][1]+b1v)));
        *(float2*)(C + (size_t)(row+8)*H_ + col + 2*t) =
          make_float2(tf32r(alpha*(c[rf][nf][2]+b0v)), tf32r(alpha*(c[rf][nf][3]+b1v)));
      }
    }
  }
}

// ---------------- score projections on GATHERED predicate rows (modes 0/1) ----------------
__global__ __launch_bounds__(256,2) void k_projS(
    const float* __restrict__ b_var, const float* __restrict__ b_sym,
    const float* __restrict__ Wsc){
  extern __shared__ float sm[];
  int mode = blockIdx.z;                 // 0 = var, 1 = sym
  int b = blockIdx.y >> 3, tile = blockIdx.y & 7;
  int cnt = g_pcnt[b];
  int m0 = tile*128;
  if (m0 >= cnt) return;
  const float* A = (mode==0) ? g_vi : g_xr;
  const float* W = g_Wr + (size_t)mode*H_*H_;
  const float* bias = (mode==0) ? b_var : b_sym;
  const float* wsc = Wsc + mode*H_;
  const int* pidx = g_pidx + b*N_;
  int tid=threadIdx.x, lane=tid&31, wid=tid>>5;
  int wr=wid&3, wc=wid>>2;
  int n0 = blockIdx.x*128;
  int sr = tid>>3, sq = (tid&7)*4;
  uint32_t smBase = (uint32_t)__cvta_generic_to_shared(sm);
  uint32_t sA0 = smBase + (sr*STP + sq)*4;
  uint32_t sA1 = sA0 + 128*STP*4;
  uint32_t sB0 = sA0 + 2*128*STP*4;
  uint32_t sB1 = sA0 + 3*128*STP*4;
  // gathered per-row A pointers (4 rows per staging thread)
  const float* gAr[4];
  #pragma unroll
  for (int i=0;i<4;i++){
    int j = m0 + sr + 32*i;
    int n = (j < cnt) ? pidx[j] : pidx[0];
    gAr[i] = A + ((size_t)(b<<10) + n)*H_ + sq;
  }
  const float* gW = W + (size_t)(n0+sr)*H_ + sq;
  int mrow = wr*32 + (lane>>2), mc = 2*(lane&3);
  int brow = wc*64 + (lane>>2);
  const float* mA0 = sm + mrow*STP + mc;
  const float* mA1 = mA0 + 128*STP;
  const float* mB0 = sm + 2*128*STP + brow*STP + mc;
  const float* mB1 = mB0 + 128*STP;
  #define STAGE_S(sa, sb) do { \
    cpa16s((sa),            gAr[0]); \
    cpa16s((sa)+32*STP*4,   gAr[1]); \
    cpa16s((sa)+64*STP*4,   gAr[2]); \
    cpa16s((sa)+96*STP*4,   gAr[3]); \
    cpa16s((sb),            gW); \
    cpa16s((sb)+32*STP*4,   gW+32*H_); \
    cpa16s((sb)+64*STP*4,   gW+64*H_); \
    cpa16s((sb)+96*STP*4,   gW+96*H_); \
    gAr[0]+=KT; gAr[1]+=KT; gAr[2]+=KT; gAr[3]+=KT; gW += KT; cp_commit(); } while(0)
  STAGE_S(sA0, sB0);
  float c[2][8][4];
  #pragma unroll
  for(int i=0;i<2;i++)
    #pragma unroll
    for(int j=0;j<8;j++){ c[i][j][0]=0;c[i][j][1]=0;c[i][j][2]=0;c[i][j][3]=0; }
  #pragma unroll 1
  for (int kt2=0; kt2<NKT/2; kt2++){
    cp_wait0(); __syncthreads();
    STAGE_S(sA1, sB1);
    mma_tile_pre<STP,8,4>(mA0, mB0, c);
    cp_wait0(); __syncthreads();
    if (kt2 < NKT/2-1) STAGE_S(sA0, sB0);
    mma_tile_pre<STP,8,4>(mA1, mB1, c);
  }
  #undef STAGE_S
  int t = lane&3;
  float p[4] = {0,0,0,0};
  #pragma unroll
  for (int rf=0; rf<2; rf++){
    #pragma unroll
    for (int nf=0; nf<8; nf++){
      int col0 = n0 + wc*64 + nf*8 + 2*t;
      float w0 = wsc[col0], w1 = wsc[col0+1];
      float b0v = bias[col0], b1v = bias[col0+1];
      p[rf*2+0] += ftanh(c[rf][nf][0]+b0v)*w0 + ftanh(c[rf][nf][1]+b1v)*w1;
      p[rf*2+1] += ftanh(c[rf][nf][2]+b0v)*w0 + ftanh(c[rf][nf][3]+b1v)*w1;
    }
  }
  #pragma unroll
  for (int i=0;i<4;i++){
    float v = p[i];
    v += __shfl_xor_sync(0xffffffffu, v, 1);
    v += __shfl_xor_sync(0xffffffffu, v, 2);
    int j = m0 + wr*32 + (i>>1)*16 + (lane>>2) + (i&1)*8;
    if (t==0 && j < cnt)
      atomicAdd(&g_sc[b*N_ + pidx[j]], v);
  }
}

// ---------------- attention pass 1 ----------------
__global__ __launch_bounds__(256,2) void k_attn1(){
  extern __shared__ float sm[];
  int tid=threadIdx.x, lane=tid&31, wid=tid>>5;
  int wr=wid&3, wc=wid>>2;
  int bh=blockIdx.x, b=bh/NH_, h=bh-b*NH_;
  int n0=blockIdx.y*128;
  const float* Q = g_Qb + (size_t)b*N_*H_ + h*64;
  const float* K = g_Kb + (size_t)b*N_*H_ + h*64;
  int sr = tid>>4, sq = (tid&15)*4;
  uint32_t smBase = (uint32_t)__cvta_generic_to_shared(sm);
  uint32_t sQ  = smBase + (sr*ST + sq)*4;
  uint32_t sK0 = sQ + 128*ST*4;
  uint32_t sK1 = sQ + 2*128*ST*4;
  const float* gQ = Q + (size_t)(n0+sr)*H_ + sq;
  const float* gK = K + (size_t)sr*H_ + sq;
  int mrow = wr*32 + (lane>>2), mc = 2*(lane&3);
  int brow = wc*64 + (lane>>2);
  const float* mQ  = sm + mrow*ST + mc;
  const float* mK0 = sm + 128*ST + brow*ST + mc;
  const float* mK1 = mK0 + 128*ST;
  #define STAGE_A(sdst) do { \
    cpa16s((sdst),           gK); \
    cpa16s((sdst)+16*ST*4,   gK+16*H_); \
    cpa16s((sdst)+32*ST*4,   gK+32*H_); \
    cpa16s((sdst)+48*ST*4,   gK+48*H_); \
    cpa16s((sdst)+64*ST*4,   gK+64*H_); \
    cpa16s((sdst)+80*ST*4,   gK+80*H_); \
    cpa16s((sdst)+96*ST*4,   gK+96*H_); \
    cpa16s((sdst)+112*ST*4,  gK+112*H_); \
    gK += 128*H_; cp_commit(); } while(0)
  #pragma unroll
  for (int it=0; it<8; it++)
    cpa16s(sQ + it*16*ST*4, gQ + it*16*H_);
  STAGE_A(sK0);
  float z[4]={0,0,0,0};
  #pragma unroll 1
  for (int mt2=0; mt2<4; mt2++){
    cp_wait0(); __syncthreads();
    STAGE_A(sK1);
    {
      float c[2][8][4];
      #pragma unroll
      for(int i=0;i<2;i++)
        #pragma unroll
        for(int j=0;j<8;j++){ c[i][j][0]=0;c[i][j][1]=0;c[i][j][2]=0;c[i][j][3]=0; }
      mma_tile_pre<ST,8,8>(mQ, mK0, c);
      #pragma unroll
      for (int rf=0; rf<2; rf++)
        #pragma unroll
        for (int nf=0; nf<8; nf++){
          z[rf*2+0] += fex2(c[rf][nf][0]) + fex2(c[rf][nf][1]);
          z[rf*2+1] += fex2(c[rf][nf][2]) + fex2(c[rf][nf][3]);
        }
    }
    cp_wait0(); __syncthreads();
    if (mt2 < 3) STAGE_A(sK0);
    {
      float c[2][8][4];
      #pragma unroll
      for(int i=0;i<2;i++)
        #pragma unroll
        for(int j=0;j<8;j++){ c[i][j][0]=0;c[i][j][1]=0;c[i][j][2]=0;c[i][j][3]=0; }
      mma_tile_pre<ST,8,8>(mQ, mK1, c);
      #pragma unroll
      for (int rf=0; rf<2; rf++)
        #pragma unroll
        for (int nf=0; nf<8; nf++){
          z[rf*2+0] += fex2(c[rf][nf][0]) + fex2(c[rf][nf][1]);
          z[rf*2+1] += fex2(c[rf][nf][2]) + fex2(c[rf][nf][3]);
        }
    }
  }
  #undef STAGE_A
  #pragma unroll
  for (int i=0;i<4;i++){
    float v = z[i];
    v += __shfl_xor_sync(0xffffffffu, v, 1);
    v += __shfl_xor_sync(0xffffffffu, v, 2);
    if ((lane&3)==0)
      atomicAdd(&g_Z[(size_t)bh*N_ + n0 + wr*32 + (i>>1)*16 + (lane>>2) + (i&1)*8], v);
  }
}

// ---------------- cross scores ----------------
__global__ __launch_bounds__(128) void k_cross(const float* __restrict__ x, const float* __restrict__ Wc,
                                               const float* __restrict__ bc, const int* __restrict__ occ){
  int pid = blockIdx.x;
  int b = pid / M_;
  int o0 = occ[pid*2], o1 = occ[pid*2+1];
  const float* x0 = x + ((size_t)b*N_+o0)*H_;
  const float* x1 = x + ((size_t)b*N_+o1)*H_;
  float p = 0.f;
  for (int h=threadIdx.x; h<H_; h+=128) p += 0.5f*(x0[h]+x1[h])*Wc[h];
  for (int o=16;o;o>>=1) p += __shfl_xor_sync(0xffffffffu, p, o);
  __shared__ float red[4];
  if ((threadIdx.x&31)==0) red[threadIdx.x>>5] = p;
  __syncthreads();
  if (threadIdx.x==0){
    float t = d_lrelu(bc[0] + red[0]+red[1]+red[2]+red[3]);
    atomicAdd(&g_vg2[b*N_+o0], t*t);
    atomicAdd(&g_vg2[b*N_+o1], t*t);
  }
}

// ---------------- band + sumw + coef ----------------
__global__ __launch_bounds__(1024) void k_post(const int* __restrict__ pp){
  __shared__ float ab[N_], wt[N_], red[32];
  __shared__ float swv;
  int b = blockIdx.x, n = threadIdx.x;
  const int* P = pp + b*N_;
  const float* s = g_sc + b*N_;
  float a = 0.f;
  if (n < N_-1){
    float sl1 = d_pred(P,n+1) ? d_lrelu(s[n+1]) : 0.f;
    bool up0 = d_pred(P,n) && (n<=1 || !d_single(P,n));
    float su0 = up0 ? d_lrelu(s[n]) : 0.f;
    a = sl1 + su0;
  }
  ab[n] = a; g_ab[b*N_+n] = a;
  bool up = d_pred(P,n) && (n<=1 || !d_single(P,n));
  bool tr = up && (n>=1);
  float w = d_pred(P,n) ? (tr?3.f:2.f) : 0.f;
  wt[n] = w;
  float v = w;
  for (int o=16;o;o>>=1) v += __shfl_xor_sync(0xffffffffu, v, o);
  if ((n&31)==0) red[n>>5] = v;
  __syncthreads();
  if (n < 32){
    float t2 = red[n];
    for (int o=16;o;o>>=1) t2 += __shfl_xor_sync(0xffffffffu, t2, o);
    if (n==0) swv = t2;
  }
  __syncthreads();
  float am1 = (n>=1) ? ab[n-1] : 0.f;
  g_dg[b*N_+n] = 0.8f*(am1*am1 + a*a) + g_vg2[b*N_+n];
  float sw = swv;
  int nm = (n+N_-1)&(N_-1), np = (n+1)&(N_-1);
  float c1 = wt[nm]*(d_single(P,nm)?1.f:0.5f) + wt[np]*(d_single(P,np)?0.f:0.5f);
  g_c1[b*N_+n] = c1 / sw;
  g_c2[b*N_+n] = wt[n] / sw;
}

// ---------------- band correction ----------------
__global__ __launch_bounds__(256) void k_bandfix(){
  int bh = blockIdx.x, b = bh/NH_, h = bh - b*NH_;
  int wid = threadIdx.x>>5, lane = threadIdx.x&31;
  int n = blockIdx.y*8 + wid;
  const float* Qr = g_Qb + ((size_t)b*N_ + n)*H_ + h*64;
  const float* Kp = g_Kb + (size_t)b*N_*H_ + h*64;
  const float* ab = g_ab + b*N_;
  float q0 = Qr[lane], q1 = Qr[lane+32];
  float anm2=(n>=2)?ab[n-2]:0.f, anm1=(n>=1)?ab[n-1]:0.f;
  float an=ab[n], anp1=(n<N_-1)?ab[n+1]:0.f;
  float biasv[5] = { LOG2E*0.8f*anm2*anm1, LOG2E*0.2f*anm1, LOG2E*g_dg[b*N_+n],
                     LOG2E*0.2f*an, LOG2E*0.8f*an*anp1 };
  float delta[5];
  float dz = 0.f;
  #pragma unroll
  for (int d=-2; d<=2; d++){
    int m = n + d;
    delta[d+2] = 0.f;
    if ((unsigned)m < (unsigned)N_){
      const float* Kr = Kp + (size_t)m*H_;
      float s = q0*Kr[lane] + q1*Kr[lane+32];
      #pragma unroll
      for (int o=16;o;o>>=1) s += __shfl_xor_sync(0xffffffffu, s, o);
      delta[d+2] = fex2(s + biasv[d+2]) - fex2(s);
      dz += delta[d+2];
    }
  }
  float Zf = g_Z[(size_t)bh*N_ + n] + dz;
  if (lane==0) g_Z[(size_t)bh*N_ + n] = Zf;
  float w1 = g_c1[b*N_+n] / Zf;
  float w2 = g_c2[b*N_+n] / Zf;
  if (lane==0 && (w1 != 0.f || w2 != 0.f)){
    #pragma unroll
    for (int d=-2; d<=2; d++){
      int m = n + d;
      if ((unsigned)m < (unsigned)N_ && delta[d+2] != 0.f){
        atomicAdd(&g_r1[(size_t)bh*N_ + m], w1*delta[d+2]);
        atomicAdd(&g_r2[(size_t)bh*N_ + m], w2*delta[d+2]);
      }
    }
  }
}

// ---------------- attention pass 2 ----------------
__global__ __launch_bounds__(256,2) void k_attn2(){
  extern __shared__ float sm[];
  float* colp = sm + 3*128*ST;
  int tid=threadIdx.x, lane=tid&31, wid=tid>>5;
  int wr=wid&3, wc=wid>>2;
  int bh=blockIdx.x, b=bh/NH_, h=bh-b*NH_;
  int m0=blockIdx.y*128;
  const float* Q = g_Qb + (size_t)b*N_*H_ + h*64;
  const float* K = g_Kb + (size_t)b*N_*H_ + h*64;
  int sr = tid>>4, sq = (tid&15)*4;
  uint32_t smBase = (uint32_t)__cvta_generic_to_shared(sm);
  uint32_t sKr = smBase + (sr*ST + sq)*4;
  uint32_t sQ0 = sKr + 128*ST*4;
  uint32_t sQ1 = sKr + 2*128*ST*4;
  const float* gKr = K + (size_t)(m0+sr)*H_ + sq;
  const float* gQ  = Q + (size_t)sr*H_ + sq;
  int mrow = wr*32 + (lane>>2), mc = 2*(lane&3);
  int brow = wc*64 + (lane>>2);
  const float* mK  = sm + mrow*ST + mc;
  const float* mQ0 = sm + 128*ST + brow*ST + mc;
  const float* mQ1 = mQ0 + 128*ST;
  int nctr = 0;
  #define STAGE_Q(sdst, cbuf) do { \
    cpa16s((sdst),           gQ); \
    cpa16s((sdst)+16*ST*4,   gQ+16*H_); \
    cpa16s((sdst)+32*ST*4,   gQ+32*H_); \
    cpa16s((sdst)+48*ST*4,   gQ+48*H_); \
    cpa16s((sdst)+64*ST*4,   gQ+64*H_); \
    cpa16s((sdst)+80*ST*4,   gQ+80*H_); \
    cpa16s((sdst)+96*ST*4,   gQ+96*H_); \
    cpa16s((sdst)+112*ST*4,  gQ+112*H_); \
    gQ += 128*H_; \
    if (tid < 128){ \
      int n = nctr*128 + tid; \
      float iz = 1.f / g_Z[(size_t)bh*N_ + n]; \
      colp[(cbuf)*256 + tid]       = g_c1[b*N_+n]*iz; \
      colp[(cbuf)*256 + 128 + tid] = g_c2[b*N_+n]*iz; \
    } \
    nctr++; cp_commit(); } while(0)
  #pragma unroll
  for (int it=0; it<8; it++)
    cpa16s(sKr + it*16*ST*4, gKr + it*16*H_);
  STAGE_Q(sQ0, 0);
  float r1[4]={0,0,0,0}, r2[4]={0,0,0,0};
  #pragma unroll 1
  for (int nt2=0; nt2<4; nt2++){
    cp_wait0(); __syncthreads();
    STAGE_Q(sQ1, 1);
    {
      float c[2][8][4];
      #pragma unroll
      for(int i=0;i<2;i++)
        #pragma unroll
        for(int j=0;j<8;j++){ c[i][j][0]=0;c[i][j][1]=0;c[i][j][2]=0;c[i][j][3]=0; }
      mma_tile_pre<ST,8,8>(mK, mQ0, c);
      const float* cp0 = colp;
      #pragma unroll
      for (int rf=0; rf<2; rf++)
        #pragma unroll
        for (int nf=0; nf<8; nf++){
          int lc0 = wc*64 + nf*8 + 2*(lane&3);
          float w1a = cp0[lc0], w1b = cp0[lc0+1];
          float w2a = cp0[128+lc0], w2b = cp0[128+lc0+1];
          float P0 = fex2(c[rf][nf][0]), P1 = fex2(c[rf][nf][1]);
          float P2 = fex2(c[rf][nf][2]), P3 = fex2(c[rf][nf][3]);
          r1[rf*2+0] += w1a*P0 + w1b*P1;  r2[rf*2+0] += w2a*P0 + w2b*P1;
          r1[rf*2+1] += w1a*P2 + w1b*P3;  r2[rf*2+1] += w2a*P2 + w2b*P3;
        }
    }
    cp_wait0(); __syncthreads();
    if (nt2 < 3) STAGE_Q(sQ0, 0);
    {
      float c[2][8][4];
      #pragma unroll
      for(int i=0;i<2;i++)
        #pragma unroll
        for(int j=0;j<8;j++){ c[i][j][0]=0;c[i][j][1]=0;c[i][j][2]=0;c[i][j][3]=0; }
      mma_tile_pre<ST,8,8>(mK, mQ1, c);
      const float* cp0 = colp + 256;
      #pragma unroll
      for (int rf=0; rf<2; rf++)
        #pragma unroll
        for (int nf=0; nf<8; nf++){
          int lc0 = wc*64 + nf*8 + 2*(lane&3);
          float w1a = cp0[lc0], w1b = cp0[lc0+1];
          float w2a = cp0[128+lc0], w2b = cp0[128+lc0+1];
          float P0 = fex2(c[rf][nf][0]), P1 = fex2(c[rf][nf][1]);
          float P2 = fex2(c[rf][nf][2]), P3 = fex2(c[rf][nf][3]);
          r1[rf*2+0] += w1a*P0 + w1b*P1;  r2[rf*2+0] += w2a*P0 + w2b*P1;
          r1[rf*2+1] += w1a*P2 + w1b*P3;  r2[rf*2+1] += w2a*P2 + w2b*P3;
        }
    }
  }
  #undef STAGE_Q
  #pragma unroll
  for (int i=0;i<4;i++){
    float v1 = r1[i], v2 = r2[i];
    v1 += __shfl_xor_sync(0xffffffffu, v1, 1);
    v1 += __shfl_xor_sync(0xffffffffu, v1, 2);
    v2 += __shfl_xor_sync(0xffffffffu, v2, 1);
    v2 += __shfl_xor_sync(0xffffffffu, v2, 2);
    if ((lane&3)==0){
      size_t o = (size_t)bh*N_ + m0 + wr*32 + (i>>1)*16 + (lane>>2) + (i&1)*8;
      atomicAdd(&g_r1[o], v1);
      atomicAdd(&g_r2[o], v2);
    }
  }
}

// ---------------- A = r @ V ----------------
__global__ __launch_bounds__(768) void k_matvec(){
  int b = blockIdx.x, f = threadIdx.x, h = f >> 6;
  int m0 = blockIdx.y*64;
  const float* r1 = g_r1 + ((size_t)b*NH_+h)*N_;
  const float* r2 = g_r2 + ((size_t)b*NH_+h)*N_;
  float a1=0.f, a2=0.f;
  for (int m=m0; m<m0+64; m++){
    float vv = g_Vb[((size_t)b*N_+m)*H_+f];
    a1 += r1[m]*vv; a2 += r2[m]*vv;
  }
  atomicAdd(&g_A1[b*H_+f], a1);
  atomicAdd(&g_A2[b*H_+f], a2);
}

// ---------------- final GEMVs ----------------
__global__ __launch_bounds__(256) void k_final1(const float* __restrict__ Wo, const float* __restrict__ bo){
  __shared__ float A1s[H_], A2s[H_];
  int b = blockIdx.x, tile = blockIdx.y;
  int tid = threadIdx.x, lane = tid&31, w = tid>>5;
  for (int i=tid; i<H_; i+=256){ A1s[i]=g_A1[b*H_+i]; A2s[i]=g_A2[b*H_+i]; }
  __syncthreads();
  #pragma unroll 1
  for (int oo=0; oo<16; oo++){
    int o = tile*128 + w*16 + oo;
    const float* wr = Wo + (size_t)o*H_;
    float u1=0.f, u2=0.f;
    #pragma unroll
    for (int k=0; k<H_/32; k++){
      float wv = wr[lane + k*32];
      u1 += wv*A1s[lane + k*32];
      u2 += wv*A2s[lane + k*32];
    }
    #pragma unroll
    for (int off=16; off; off>>=1){
      u1 += __shfl_xor_sync(0xffffffffu, u1, off);
      u2 += __shfl_xor_sync(0xffffffffu, u2, off);
    }
    if (lane==0){
      g_u1[b*H_+o] = u1 + bo[o];
      g_u2[b*H_+o] = u2 + bo[o];
    }
  }
}

__global__ __launch_bounds__(256) void k_final2(const float* __restrict__ Wa, const float* __restrict__ ba,
                                                float* __restrict__ out){
  __shared__ float u1s[H_], u2s[H_], pms[128];
  int b = blockIdx.x, tile = blockIdx.y;
  int tid = threadIdx.x, lane = tid&31, w = tid>>5;
  for (int i=tid; i<H_; i+=256){ u1s[i]=g_u1[b*H_+i]; u2s[i]=g_u2[b*H_+i]; }
  __syncthreads();
  #pragma unroll 1
  for (int oo=0; oo<16; oo++){
    int o = tile*128 + w*16 + oo;
    const float* wa = Wa + (size_t)o*2*H_;
    float p = 0.f;
    #pragma unroll
    for (int k=0; k<H_/32; k++){
      p += wa[lane + k*32]*u1s[lane + k*32];
      p += wa[H_ + lane + k*32]*u2s[lane + k*32];
    }
    #pragma unroll
    for (int off=16; off; off>>=1)
      p += __shfl_xor_sync(0xffffffffu, p, off);
    if (lane==0) pms[w*16 + oo] = p + ba[o];
  }
  __syncthreads();
  int f0 = tile*128;
  float4 v0 = *(float4*)(pms + (tid&31)*4);
  int rowstart = tid>>5;
  for (int n = rowstart; n < N_; n += 8){
    *(float4*)(out + ((size_t)b*N_ + n)*H_ + f0 + (tid&31)*4) = v0;
  }
}

// ---------------- launch ----------------
extern "C" void kernel_launch(void* const* d_in, const int* in_sizes, int n_in,
                              void* d_out, int out_size){
  (void)in_sizes; (void)n_in; (void)out_size;
  const float* x      = (const float*)d_in[0];
  const float* W_var  = (const float*)d_in[3];
  const float* b_var  = (const float*)d_in[4];
  const float* W_sym  = (const float*)d_in[5];
  const float* b_sym  = (const float*)d_in[6];
  const float* W_sc   = (const float*)d_in[7];
  const float* b_scb  = (const float*)d_in[8];
  const float* W_cr   = (const float*)d_in[9];
  const float* b_cr   = (const float*)d_in[10];
  const float* W_atom = (const float*)d_in[11];
  const float* b_atom = (const float*)d_in[12];
  const float* W_q    = (const float*)d_in[13];
  const float* b_q    = (const float*)d_in[14];
  const float* W_k    = (const float*)d_in[15];
  const float* b_k    = (const float*)d_in[16];
  const float* W_v    = (const float*)d_in[17];
  const float* b_v    = (const float*)d_in[18];
  const float* W_o    = (const float*)d_in[19];
  const float* b_o    = (const float*)d_in[20];
  const int*   pp     = (const int*)d_in[21];
  const int*   occ    = (const int*)d_in[24];
  float* out = (float*)d_out;

  float *p_Q, *p_K, *p_V;
  cudaGetSymbolAddress((void**)&p_Q, g_Qb);
  cudaGetSymbolAddress((void**)&p_K, g_Kb);
  cudaGetSymbolAddress((void**)&p_V, g_Vb);

  const int PROJ_SMEM  = (4*128*STP)*4;
  const int ATTN1_SMEM = (3*128*ST)*4;
  const int ATTN2_SMEM = (3*128*ST + 512)*4;
  static bool attr_done = false;
  static cudaStream_t s2 = nullptr;
  static cudaEvent_t eF = nullptr, eJ = nullptr;
  if (!attr_done){
    cudaFuncSetAttribute(k_proj,  cudaFuncAttributeMaxDynamicSharedMemorySize, PROJ_SMEM);
    cudaFuncSetAttribute(k_projS, cudaFuncAttributeMaxDynamicSharedMemorySize, PROJ_SMEM);
    cudaFuncSetAttribute(k_attn1, cudaFuncAttributeMaxDynamicSharedMemorySize, ATTN1_SMEM);
    cudaFuncSetAttribute(k_attn2, cudaFuncAttributeMaxDynamicSharedMemorySize, ATTN2_SMEM);
    cudaStreamCreateWithFlags(&s2, cudaStreamNonBlocking);
    cudaEventCreateWithFlags(&eF, cudaEventDisableTiming);
    cudaEventCreateWithFlags(&eJ, cudaEventDisableTiming);
    attr_done = true;
  }

  k_init<<<(B_*NH_*N_+255)/256, 256>>>(b_scb);
  const int PRE = 2*(B_*N_*H_/8) + 5*(H_*H_/8);
  k_preconv<<<(PRE+255)/256, 256>>>(x, pp, W_var, W_sym, W_q, W_k, W_v);
  cudaEventRecord(eF, 0);
  cudaStreamWaitEvent(s2, eF, 0);
  // side stream: predicate-gathered score GEMMs, V projection, cross, post
  k_plist<<<B_, 1024, 0, s2>>>(pp);
  dim3 gpS(H_/128, B_*8, 2);
  k_projS<<<gpS, 256, PROJ_SMEM, s2>>>(b_var, b_sym, W_sc);
  dim3 gpV(H_/128, (B_*N_)/128, 1);
  k_proj<<<gpV, 256, PROJ_SMEM, s2>>>(b_q, b_k, b_v, p_Q, p_K, p_V, 1);
  k_cross<<<B_*M_, 128, 0, s2>>>(x, W_cr, b_cr, occ);
  k_post<<<B_, 1024, 0, s2>>>(pp);
  // main stream: Q/K projections + attn1
  dim3 gpQK(H_/128, (B_*N_)/128, 2);
  k_proj<<<gpQK, 256, PROJ_SMEM>>>(b_q, b_k, b_v, p_Q, p_K, p_V, 0);
  dim3 ga(B_*NH_, N_/128);
  k_attn1<<<ga, 256, ATTN1_SMEM>>>();
  cudaEventRecord(eJ, s2);
  cudaStreamWaitEvent(0, eJ, 0);
  dim3 gbf(B_*NH_, N_/8);
  k_bandfix<<<gbf, 256>>>();
  k_attn2<<<ga, 256, ATTN2_SMEM>>>();
  dim3 gmv(B_, 16);
  k_matvec<<<gmv, 768>>>();
  dim3 gf(B_, H_/128);
  k_final1<<<gf, 256>>>(W_o, b_o);
  k_final2<<<gf, 256>>>(W_atom, b_atom, out);
}